// round 2
// baseline (speedup 1.0000x reference)
#include <cuda_runtime.h>
#include <math.h>

// ---------------------------------------------------------------------------
// Conv2dODENet dopri5 Neural ODE — single persistent kernel (1 graph node).
#define BB 8
#define CC 64
#define FF 128
#define OUTC 10
#define NPIX 32768
#define NY (NPIX*CC)         // 2097152
#define NH (NPIX*FF)         // 4194304
#define GRIDN 296
#define NT 256
#define NITER 32

// ----------------------------- device state --------------------------------
__device__ float g_y[NY];
__device__ float g_y5[NY];
__device__ float g_k[7][NY];
__device__ float g_h1[NH];
__device__ float g_h2[NH];
__device__ float g_S2[9*FF];
__device__ float g_partial[GRIDN];
__device__ float g_t, g_h, g_hs;
__device__ int   g_done, g_accept;
__device__ unsigned g_bar_in, g_bar_gen;

// stage-combination coefficients: row s = coeffs to build input of stage s
__constant__ float c_comb[7][6] = {
  { 0,0,0,0,0,0 },
  { (float)(1.0/5.0), 0,0,0,0,0 },
  { (float)(3.0/40.0), (float)(9.0/40.0), 0,0,0,0 },
  { (float)(44.0/45.0), (float)(-56.0/15.0), (float)(32.0/9.0), 0,0,0 },
  { (float)(19372.0/6561.0), (float)(-25360.0/2187.0), (float)(64448.0/6561.0),
    (float)(-212.0/729.0), 0,0 },
  { (float)(9017.0/3168.0), (float)(-355.0/33.0), (float)(46732.0/5247.0),
    (float)(49.0/176.0), (float)(-5103.0/18656.0), 0 },
  { (float)(35.0/384.0), 0.0f, (float)(500.0/1113.0), (float)(125.0/192.0),
    (float)(-2187.0/6784.0), (float)(11.0/84.0) },
};
__constant__ float c_cs[7] = { 0.0f, (float)(1.0/5.0), (float)(3.0/10.0),
  (float)(4.0/5.0), (float)(8.0/9.0), 1.0f, 1.0f };

#define E1f ((float)(71.0/57600.0))
#define E3f ((float)(-71.0/16695.0))
#define E4f ((float)(71.0/1920.0))
#define E5f ((float)(-17253.0/339200.0))
#define E6f ((float)(22.0/525.0))
#define E7f ((float)(-1.0/40.0))
#define TOLf 1e-3f

// ----------------------------- grid barrier --------------------------------
// __threadfence() is gpu-scope (>= cluster) -> emits CCTL.IVALL on sm_103a,
// flushing L1D, so cached loads after the barrier see other blocks' writes.
__device__ __forceinline__ void gbar() {
  __syncthreads();
  if (threadIdx.x == 0) {
    __threadfence();  // release: make this block's writes visible device-wide
    unsigned gen = *(volatile unsigned*)&g_bar_gen;
    if (atomicAdd(&g_bar_in, 1u) == GRIDN - 1u) {
      g_bar_in = 0u;
      __threadfence();
      *(volatile unsigned*)&g_bar_gen = gen + 1u;
    } else {
      while (*(volatile unsigned*)&g_bar_gen == gen) { __nanosleep(64); }
    }
    __threadfence();  // acquire: invalidate L1D before subsequent reads
  }
  __syncthreads();
}

// ----------------------------- conv1: 1x1, 65->128, ReLU -------------------
// Input = y + hs * sum_j comb[s][j]*k[j] (combine fused into A-tile load).
// Stage 6 additionally stores that combined input as y5.
__device__ void phase_conv1(int s, float hs, float ts,
    const float* __restrict__ w1, const float* __restrict__ b1, float* sp) {
  float* As = sp;            // [16][64]
  float* Bs = sp + 1024;     // [16][128]
  const int t = threadIdx.x;
  const int tx = t & 15, ty = t >> 4;
  const int p0 = tx*4, f0 = ty*8;
  const int am = t >> 2, aq = t & 3;
  float hc[6];
  #pragma unroll
  for (int j = 0; j < 6; j++) hc[j] = hs * c_comb[s][j];
  float bias[8];
  #pragma unroll
  for (int j = 0; j < 8; j++) bias[j] = b1[f0+j] + ts * w1[f0+j];  // cin 0 = time

  for (int tile = blockIdx.x; tile < NPIX/64; tile += GRIDN) {
    int m0 = tile * 64;
    float acc[4][8];
    #pragma unroll
    for (int i = 0; i < 4; i++)
      #pragma unroll
      for (int j = 0; j < 8; j++) acc[i][j] = 0.0f;

    for (int kk = 0; kk < 64; kk += 16) {
      { // A tile: 64 pix x 16 cin, combined input
        int fi = (m0 + am)*16 + (kk >> 2) + aq;
        float4 a = ((const float4*)g_y)[fi];
        if (s > 0) {
          #pragma unroll
          for (int j = 0; j < 6; j++) {
            if (j >= s) break;          // stage s uses k[0..s-1] (s=6 uses 6)
            float c = hc[j];
            if (c != 0.0f) {
              float4 kv = ((const float4*)g_k[j])[fi];
              a.x = fmaf(c, kv.x, a.x); a.y = fmaf(c, kv.y, a.y);
              a.z = fmaf(c, kv.z, a.z); a.w = fmaf(c, kv.w, a.w);
            }
          }
          if (s == 6) ((float4*)g_y5)[fi] = a;
        }
        As[(aq*4+0)*64+am]=a.x; As[(aq*4+1)*64+am]=a.y;
        As[(aq*4+2)*64+am]=a.z; As[(aq*4+3)*64+am]=a.w;
      }
      #pragma unroll
      for (int r = 0; r < 2; r++) { // B: 16 cin x 128 f (skip time row)
        int id = t + 256*r;
        int n4 = id & 31, k = id >> 5;
        *(float4*)&Bs[k*128 + n4*4] = *(const float4*)&w1[(1 + kk + k)*FF + n4*4];
      }
      __syncthreads();
      #pragma unroll
      for (int k = 0; k < 16; k++) {
        float4 ra = *(float4*)&As[k*64 + p0];
        float4 wa = *(float4*)&Bs[k*128 + f0];
        float4 wb = *(float4*)&Bs[k*128 + f0 + 4];
        float rv[4] = {ra.x, ra.y, ra.z, ra.w};
        #pragma unroll
        for (int i = 0; i < 4; i++) {
          acc[i][0]=fmaf(rv[i],wa.x,acc[i][0]); acc[i][1]=fmaf(rv[i],wa.y,acc[i][1]);
          acc[i][2]=fmaf(rv[i],wa.z,acc[i][2]); acc[i][3]=fmaf(rv[i],wa.w,acc[i][3]);
          acc[i][4]=fmaf(rv[i],wb.x,acc[i][4]); acc[i][5]=fmaf(rv[i],wb.y,acc[i][5]);
          acc[i][6]=fmaf(rv[i],wb.z,acc[i][6]); acc[i][7]=fmaf(rv[i],wb.w,acc[i][7]);
        }
      }
      __syncthreads();
    }
    #pragma unroll
    for (int i = 0; i < 4; i++) {
      int p = m0 + p0 + i;
      float o[8];
      #pragma unroll
      for (int j = 0; j < 8; j++) { float v = acc[i][j] + bias[j]; o[j] = v > 0.f ? v : 0.f; }
      float4* dst = (float4*)&g_h1[(size_t)p*FF + f0];
      dst[0] = make_float4(o[0],o[1],o[2],o[3]);
      dst[1] = make_float4(o[4],o[5],o[6],o[7]);
    }
  }
}

// ----------------------------- conv2: 3x3 SAME, 129->128, ReLU -------------
__device__ void phase_conv2(float ts,
    const float* __restrict__ w2, const float* __restrict__ b2, float* sp) {
  float* in_s = sp;              // [16][68]
  float* w_s  = sp + 16*68;      // [3][16][128]
  const int t = threadIdx.x;
  const int tx = t & 15, ty = t >> 4;
  const int p0 = tx*4, f0 = ty*8;

  for (int tile = blockIdx.x; tile < 512; tile += GRIDN) {
    int b = tile >> 6, y = tile & 63;
    float acc[4][8];
    #pragma unroll
    for (int i = 0; i < 4; i++)
      #pragma unroll
      for (int j = 0; j < 8; j++) acc[i][j] = 0.0f;

    for (int dy = 0; dy < 3; dy++) {
      int yy = y + dy - 1;
      if (yy < 0 || yy > 63) continue;   // uniform per block
      const float* inrow = &g_h1[(size_t)((b<<6) + yy)*64*FF];
      const float* wdy   = &w2[(size_t)(dy*3)*129*FF];
      for (int ch = 0; ch < 8; ch++) {
        int c0 = ch*16;
        #pragma unroll
        for (int r = 0; r < 2; r++) {   // halo: 66 x-pos x 16 cin
          int id = t + 256*r;
          if (id < 264) {
            int xp = id >> 2, cq = id & 3, xx = xp - 1;
            float4 v = make_float4(0.f,0.f,0.f,0.f);
            if (xx >= 0 && xx < 64) v = *(const float4*)&inrow[(size_t)xx*FF + c0 + cq*4];
            in_s[(cq*4+0)*68+xp]=v.x; in_s[(cq*4+1)*68+xp]=v.y;
            in_s[(cq*4+2)*68+xp]=v.z; in_s[(cq*4+3)*68+xp]=v.w;
          }
        }
        #pragma unroll
        for (int r = 0; r < 6; r++) {   // weights: 3 dx x 16 cin x 128 f
          int id = t + 256*r;
          int f4i = id & 31, cw = (id >> 5) & 15, dx = id >> 9;
          *(float4*)&w_s[(dx*16 + cw)*128 + f4i*4] =
            *(const float4*)&wdy[((size_t)dx*129 + 1 + c0 + cw)*FF + f4i*4];
        }
        __syncthreads();
        #pragma unroll
        for (int c = 0; c < 16; c++) {
          #pragma unroll
          for (int dx = 0; dx < 3; dx++) {
            float4 wa = *(float4*)&w_s[(dx*16+c)*128 + f0];
            float4 wb = *(float4*)&w_s[(dx*16+c)*128 + f0 + 4];
            #pragma unroll
            for (int i = 0; i < 4; i++) {
              float a = in_s[c*68 + p0 + i + dx];
              acc[i][0]=fmaf(a,wa.x,acc[i][0]); acc[i][1]=fmaf(a,wa.y,acc[i][1]);
              acc[i][2]=fmaf(a,wa.z,acc[i][2]); acc[i][3]=fmaf(a,wa.w,acc[i][3]);
              acc[i][4]=fmaf(a,wb.x,acc[i][4]); acc[i][5]=fmaf(a,wb.y,acc[i][5]);
              acc[i][6]=fmaf(a,wb.z,acc[i][6]); acc[i][7]=fmaf(a,wb.w,acc[i][7]);
            }
          }
        }
        __syncthreads();
      }
    }
    int cy = (y == 0) ? 0 : ((y == 63) ? 2 : 1);
    #pragma unroll
    for (int i = 0; i < 4; i++) {
      int x = p0 + i;
      int cx = (x == 0) ? 0 : ((x == 63) ? 2 : 1);
      const float* S = &g_S2[(cy*3+cx)*FF];
      float o[8];
      #pragma unroll
      for (int j = 0; j < 8; j++) {
        float v = acc[i][j] + b2[f0+j] + ts*S[f0+j];
        o[j] = v > 0.f ? v : 0.f;
      }
      float4* dst = (float4*)&g_h2[((size_t)((b*64+y)*64 + x))*FF + f0];
      dst[0] = make_float4(o[0],o[1],o[2],o[3]);
      dst[1] = make_float4(o[4],o[5],o[6],o[7]);
    }
  }
}

// ----------------------------- conv3: 1x1, 129->64 -------------------------
__device__ void phase_conv3(int s, float ts,
    const float* __restrict__ w3, const float* __restrict__ b3, float* sp) {
  float* As = sp;            // [16][64]
  float* Bs = sp + 1024;     // [16][64]
  const int t = threadIdx.x;
  const int tx = t & 15, ty = t >> 4;
  const int p0 = tx*4, f0 = ty*4;
  const int am = t >> 2, aq = t & 3;
  float bias[4];
  #pragma unroll
  for (int j = 0; j < 4; j++) bias[j] = b3[f0+j] + ts*w3[f0+j];
  float* kout = g_k[s];

  for (int tile = blockIdx.x; tile < NPIX/64; tile += GRIDN) {
    int m0 = tile * 64;
    float acc[4][4];
    #pragma unroll
    for (int i = 0; i < 4; i++)
      #pragma unroll
      for (int j = 0; j < 4; j++) acc[i][j] = 0.0f;

    for (int kk = 0; kk < 128; kk += 16) {
      {
        float4 v = *(const float4*)&g_h2[(size_t)(m0+am)*FF + kk + aq*4];
        As[(aq*4+0)*64+am]=v.x; As[(aq*4+1)*64+am]=v.y;
        As[(aq*4+2)*64+am]=v.z; As[(aq*4+3)*64+am]=v.w;
      }
      {
        int n4 = t & 15, k = t >> 4;
        *(float4*)&Bs[k*64 + n4*4] = *(const float4*)&w3[(1 + kk + k)*CC + n4*4];
      }
      __syncthreads();
      #pragma unroll
      for (int k = 0; k < 16; k++) {
        float4 ra = *(float4*)&As[k*64 + p0];
        float4 wa = *(float4*)&Bs[k*64 + f0];
        float rv[4] = {ra.x, ra.y, ra.z, ra.w};
        #pragma unroll
        for (int i = 0; i < 4; i++) {
          acc[i][0]=fmaf(rv[i],wa.x,acc[i][0]); acc[i][1]=fmaf(rv[i],wa.y,acc[i][1]);
          acc[i][2]=fmaf(rv[i],wa.z,acc[i][2]); acc[i][3]=fmaf(rv[i],wa.w,acc[i][3]);
        }
      }
      __syncthreads();
    }
    #pragma unroll
    for (int i = 0; i < 4; i++) {
      int p = m0 + p0 + i;
      *(float4*)&kout[(size_t)p*CC + f0] = make_float4(
        acc[i][0]+bias[0], acc[i][1]+bias[1], acc[i][2]+bias[2], acc[i][3]+bias[3]);
    }
  }
}

// ----------------------------- error partial -------------------------------
__device__ void phase_err(float hs, float* sp) {
  const int t = threadIdx.x;
  float s = 0.0f;
  const float4* k1 = (const float4*)g_k[0];
  const float4* k3 = (const float4*)g_k[2];
  const float4* k4 = (const float4*)g_k[3];
  const float4* k5 = (const float4*)g_k[4];
  const float4* k6 = (const float4*)g_k[5];
  const float4* k7 = (const float4*)g_k[6];
  const float4* yv = (const float4*)g_y;
  const float4* y5 = (const float4*)g_y5;
  for (int i = blockIdx.x*NT + t; i < NY/4; i += GRIDN*NT) {
    float4 a=k1[i], c3=k3[i], c4=k4[i], c5=k5[i], c6=k6[i], c7=k7[i];
    float4 yy=yv[i], z5=y5[i];
    #define ECOMP(M) { \
      float err = hs*(E1f*a.M + E3f*c3.M + E4f*c4.M + E5f*c5.M + E6f*c6.M + E7f*c7.M); \
      float sc = TOLf + TOLf*fmaxf(fabsf(yy.M), fabsf(z5.M)); \
      float r = err/sc; s = fmaf(r, r, s); }
    ECOMP(x) ECOMP(y) ECOMP(z) ECOMP(w)
    #undef ECOMP
  }
  sp[t] = s;
  __syncthreads();
  for (int o = 128; o > 0; o >>= 1) {
    if (t < o) sp[t] += sp[t + o];
    __syncthreads();
  }
  if (t == 0) g_partial[blockIdx.x] = sp[0];
  __syncthreads();
}

// ----------------------------- main persistent kernel ----------------------
__global__ void __launch_bounds__(NT, 2) ode_all(
    const float* __restrict__ x,
    const float* __restrict__ w1, const float* __restrict__ b1,
    const float* __restrict__ w2, const float* __restrict__ b2,
    const float* __restrict__ w3, const float* __restrict__ b3,
    const float* __restrict__ wo, const float* __restrict__ bo,
    float* __restrict__ out) {
  __shared__ float sp[7232];   // 28.9 KB pool shared by all phases
  const int bid = blockIdx.x, t = threadIdx.x;

  // ---- init: y = x, S2 tap sums, control scalars
  for (int i = bid*NT + t; i < NY/4; i += GRIDN*NT)
    ((float4*)g_y)[i] = ((const float4*)x)[i];
  if (bid == 0) {
    if (t < FF) {
      int f = t;
      for (int cy = 0; cy < 3; cy++)
        for (int cx = 0; cx < 3; cx++) {
          float s = 0.0f;
          for (int dy = 0; dy < 3; dy++) {
            if (cy == 0 && dy == 0) continue;
            if (cy == 2 && dy == 2) continue;
            for (int dx = 0; dx < 3; dx++) {
              if (cx == 0 && dx == 0) continue;
              if (cx == 2 && dx == 2) continue;
              s += w2[((size_t)(dy*3+dx)*129 + 0)*FF + f];
            }
          }
          g_S2[(cy*3+cx)*FF + f] = s;
        }
    }
    if (t == 0) { g_t = 0.0f; g_h = 0.1f; g_hs = 0.1f; g_done = 0; g_accept = 0; }
  }
  gbar();

  for (int iter = 0; iter < NITER; iter++) {
    if (*(volatile int*)&g_done) break;     // uniform across grid (post-barrier)
    float hs = *(volatile float*)&g_hs;
    float tc = *(volatile float*)&g_t;

    for (int s = 0; s < 7; s++) {
      float ts = tc + c_cs[s]*hs;
      phase_conv1(s, hs, ts, w1, b1, sp);
      gbar();
      phase_conv2(ts, w2, b2, sp);
      gbar();
      phase_conv3(s, ts, w3, b3, sp);
      gbar();
    }
    phase_err(hs, sp);
    gbar();

    if (bid == 0) {   // control
      float ssum = 0.0f;
      for (int i = t; i < GRIDN; i += NT) ssum += g_partial[i];
      sp[t] = ssum;
      __syncthreads();
      for (int o = 128; o > 0; o >>= 1) {
        if (t < o) sp[t] += sp[t + o];
        __syncthreads();
      }
      if (t == 0) {
        float en = sqrtf(sp[0] / (float)NY);
        float hcur = g_hs;
        int acc = (en <= 1.0f) ? 1 : 0;
        g_accept = acc;
        float tn = acc ? (g_t + hcur) : g_t;
        g_t = tn;
        float ens = fmaxf(en, 1e-8f);
        float fac = fminf(fmaxf(0.9f * powf(ens, -0.2f), 0.2f), 10.0f);
        float hn = fmaxf(hcur * fac, 1e-4f);
        g_h = hn;
        g_done = (tn >= 1.0f) ? 1 : 0;
        g_hs = fminf(hn, 1.0f - tn);
      }
    }
    gbar();

    if (*(volatile int*)&g_accept) {
      for (int i = bid*NT + t; i < NY/4; i += GRIDN*NT)
        ((float4*)g_y)[i] = ((const float4*)g_y5)[i];
    }
    gbar();
  }

  // ---- output head: 1x1 conv 64 -> 10
  {
    float* ws = sp;          // 640
    float* bs = sp + 640;    // 10
    for (int i = t; i < CC*OUTC; i += NT) ws[i] = wo[i];
    if (t < OUTC) bs[t] = bo[t];
    __syncthreads();
    for (int p = bid*NT + t; p < NPIX; p += GRIDN*NT) {
      float accs[OUTC];
      #pragma unroll
      for (int j = 0; j < OUTC; j++) accs[j] = bs[j];
      #pragma unroll
      for (int c4 = 0; c4 < 16; c4++) {
        float4 v = *(const float4*)&g_y[(size_t)p*CC + c4*4];
        float vv[4] = {v.x, v.y, v.z, v.w};
        #pragma unroll
        for (int q = 0; q < 4; q++)
          #pragma unroll
          for (int j = 0; j < OUTC; j++)
            accs[j] = fmaf(vv[q], ws[(c4*4+q)*OUTC + j], accs[j]);
      }
      #pragma unroll
      for (int j = 0; j < OUTC; j++) out[(size_t)p*OUTC + j] = accs[j];
    }
  }
}

// ----------------------------- launcher -------------------------------------
extern "C" void kernel_launch(void* const* d_in, const int* in_sizes, int n_in,
                              void* d_out, int out_size) {
  const float* x  = (const float*)d_in[0];
  const float* w1 = (const float*)d_in[1];
  const float* b1 = (const float*)d_in[2];
  const float* w2 = (const float*)d_in[3];
  const float* b2 = (const float*)d_in[4];
  const float* w3 = (const float*)d_in[5];
  const float* b3 = (const float*)d_in[6];
  const float* wo = (const float*)d_in[7];
  const float* bo = (const float*)d_in[8];
  float* out = (float*)d_out;

  ode_all<<<GRIDN, NT>>>(x, w1, b1, w2, b2, w3, b3, wo, bo, out);
}